// round 9
// baseline (speedup 1.0000x reference)
#include <cuda_runtime.h>
#include <cuda_bf16.h>

// Problem constants (fixed by setup_inputs)
#define B_CHAIN 16384
#define S_SIDE  15
#define NATM    (1 + B_CHAIN + B_CHAIN * S_SIDE)   // 262145
#define NBLK    128
#define CHUNK   (B_CHAIN / NBLK)                   // 128 gen0 atoms / chains per block
#define K2_THR  512                                // 128 chains x 4 lanes

// Cross-kernel scratch (no cudaMalloc allowed)
__device__ float g_btot[NBLK * 12];      // per-block gen0 chunk totals

// C = A @ B for 3x4 rigid transforms, row-major [r00 r01 r02 tx | r1x | r2x]
__device__ __forceinline__ void compose(const float* __restrict__ A,
                                        const float* __restrict__ B,
                                        float* __restrict__ C) {
#pragma unroll
    for (int r = 0; r < 3; r++) {
        float a0 = A[r*4+0], a1 = A[r*4+1], a2 = A[r*4+2], a3 = A[r*4+3];
        C[r*4+0] = a0*B[0] + a1*B[4] + a2*B[8];
        C[r*4+1] = a0*B[1] + a1*B[5] + a2*B[9];
        C[r*4+2] = a0*B[2] + a1*B[6] + a2*B[10];
        C[r*4+3] = a0*B[3] + a1*B[7] + a2*B[11] + a3;
    }
}

__device__ __forceinline__ void mat_copy(float* __restrict__ d, const float* __restrict__ s) {
#pragma unroll
    for (int k = 0; k < 12; k++) d[k] = s[k];
}

__device__ __forceinline__ void mat_ident(float* __restrict__ d) {
    d[0]=1.f; d[1]=0.f; d[2]=0.f; d[3]=0.f;
    d[4]=0.f; d[5]=1.f; d[6]=0.f; d[7]=0.f;
    d[8]=0.f; d[9]=0.f; d[10]=1.f; d[11]=0.f;
}

// Bond transform: Rx(d0) Rz(d1) T(d2,0,0) Rx(d3), closed form.
// FAST uses __sincosf: side chains only (depth <= 15). Gen0 chain (16K deep)
// uses accurate sincosf — fast trig there measured rel_err 9e-4 (too close to 1e-3).
template <bool FAST>
__device__ __forceinline__ void bond_ht(float d0, float d1, float d2, float d3,
                                        float* __restrict__ M) {
    float sa, ca, sb, cb, sd, cd;
    if (FAST) {
        __sincosf(d0, &sa, &ca);
        __sincosf(d1, &sb, &cb);
        __sincosf(d3, &sd, &cd);
    } else {
        sincosf(d0, &sa, &ca);
        sincosf(d1, &sb, &cb);
        sincosf(d3, &sd, &cd);
    }
    M[0] = cb;     M[1] = -sb*cd;            M[2]  = sb*sd;             M[3]  = d2*cb;
    M[4] = ca*sb;  M[5] = ca*cb*cd - sa*sd;  M[6]  = -ca*cb*sd - sa*cd; M[7]  = ca*d2*sb;
    M[8] = sa*sb;  M[9] = sa*cb*cd + ca*sd;  M[10] = -sa*cb*sd + ca*cd; M[11] = sa*d2*sb;
}

// Atom 1 jump (d4=d5=0): T(d0,d1,d2) @ Rx(d3)
__device__ __forceinline__ void jump_ht(float d0, float d1, float d2, float d3,
                                        float* __restrict__ M) {
    float sd, cd; sincosf(d3, &sd, &cd);
    M[0] = 1.f; M[1] = 0.f; M[2] = 0.f;  M[3]  = d0;
    M[4] = 0.f; M[5] = cd;  M[6] = -sd;  M[7]  = d1;
    M[8] = 0.f; M[9] = sd;  M[10] = cd;  M[11] = d2;
}

__device__ __forceinline__ void shfl_up_mat(float* __restrict__ P,
                                            const float* __restrict__ M,
                                            int off, int width) {
#pragma unroll
    for (int k = 0; k < 12; k++)
        P[k] = __shfl_up_sync(0xffffffffu, M[k], off, width);
}

__device__ __forceinline__ void shfl_dn_mat(float* __restrict__ P,
                                            const float* __restrict__ M,
                                            int off) {
#pragma unroll
    for (int k = 0; k < 12; k++)
        P[k] = __shfl_down_sync(0xffffffffu, M[k], off);
}

// Local ht for gen0 index gi (atom gi+1), accurate trig
__device__ __forceinline__ void gen0_ht(const float* __restrict__ dofs,
                                        int gi, float* __restrict__ M) {
    const float4 d = __ldg((const float4*)(dofs + 4 * gi));
    if (gi == 0) jump_ht(d.x, d.y, d.z, d.w, M);
    else         bond_ht<false>(d.x, d.y, d.z, d.w, M);
}

// Warp inclusive scan (order-preserving, width 32)
__device__ __forceinline__ void warp_scan(float* __restrict__ M, int lane) {
#pragma unroll
    for (int off = 1; off < 32; off <<= 1) {
        float P[12], C[12];
        shfl_up_mat(P, M, off, 32);
        compose(P, M, C);
        if (lane >= off) mat_copy(M, C);
    }
}

// ---------------- K1: per-block chunk totals only ----------------
__global__ void __launch_bounds__(CHUNK) k_totals(const float* __restrict__ dofs) {
    __shared__ float s_w[4 * 12];
    const int tid  = threadIdx.x;
    const int lane = tid & 31;
    const int wid  = tid >> 5;
    const int gi   = blockIdx.x * CHUNK + tid;

    float M[12];
    gen0_ht(dofs, gi, M);

    // warp product reduction (order-preserving): lane0 ends with v0∘...∘v31
#pragma unroll
    for (int off = 1; off < 32; off <<= 1) {
        float P[12], C[12];
        shfl_dn_mat(P, M, off);
        compose(M, P, C);
        mat_copy(M, C);           // upper lanes hold garbage; lane0 correct
    }
    if (lane == 0) mat_copy(&s_w[wid * 12], M);
    __syncthreads();

    if (tid == 0) {
        float T[12], C[12];
        mat_copy(T, &s_w[0]);
#pragma unroll
        for (int i = 1; i < 4; i++) { compose(T, &s_w[i * 12], C); mat_copy(T, C); }
        mat_copy(&g_btot[blockIdx.x * 12], T);
    }
}

// ---------------- K2: scan-redo + prefix + apply (4 lanes/chain) ----------------
__global__ void __launch_bounds__(K2_THR)
k_apply(const float* __restrict__ dofs,
        const int* __restrict__ kin_id,
        float* __restrict__ out) {
    __shared__ float s_scan[CHUNK * 12];    // 6 KB: chunk inclusive scans
    __shared__ float s_wA[4 * 12];          // warp totals, group A
    __shared__ float s_wB[4 * 12];          // warp totals, group B
    __shared__ float s_pref[12];            // exclusive prefix for this block

    const int b    = blockIdx.x;
    const int tid  = threadIdx.x;
    const int lane = tid & 31;

    float MA[12], MB[12];

    if (tid < CHUNK) {
        // ---- Group A (warps 0-3): recompute chunk inclusive scan (accurate) ----
        gen0_ht(dofs, b * CHUNK + tid, MA);
        warp_scan(MA, lane);
        if (lane == 31) mat_copy(&s_wA[(tid >> 5) * 12], MA);
    } else if (tid < 2 * CHUNK) {
        // ---- Group B (warps 4-7): scan the 128 block totals ----
        const int t2 = tid - CHUNK;
        mat_copy(MB, &g_btot[t2 * 12]);
        warp_scan(MB, lane);
        if (lane == 31) mat_copy(&s_wB[(t2 >> 5) * 12], MB);
    }
    __syncthreads();

    if (tid < CHUNK) {
        const int wid = tid >> 5;
        float W[12]; mat_ident(W);
        for (int i = 0; i < wid; i++) {
            float C[12]; compose(W, &s_wA[i * 12], C); mat_copy(W, C);
        }
        float F[12]; compose(W, MA, F);
        mat_copy(&s_scan[tid * 12], F);
    } else if (tid < 2 * CHUNK) {
        const int t2  = tid - CHUNK;
        const int wid = t2 >> 5;
        float W[12]; mat_ident(W);
        for (int i = 0; i < wid; i++) {
            float C[12]; compose(W, &s_wB[i * 12], C); mat_copy(W, C);
        }
        float F[12]; compose(W, MB, F);      // inclusive over btot[0..t2]
        if (b == 0) {
            if (t2 == 0) { float I[12]; mat_ident(I); mat_copy(s_pref, I); }
        } else if (t2 == b - 1) {
            mat_copy(s_pref, F);
        }
    }
    __syncthreads();

    // ---- Phase 3: 4 lanes per chain, 4 atoms serial per lane ----
    // lane 0: parent (gen0 global) + side atoms 0..2
    // lane j>0: side atoms 3+(j-1)*4 .. 3+(j-1)*4+3
    const int l = tid >> 2;            // local chain 0..127
    const int j = tid & 3;             // lane within chain
    const int c = b * CHUNK + l;       // global chain
    const int sbase = B_CHAIN + c * S_SIDE;        // dof row of side atom 0
    const int first = (j == 0) ? 0 : 3 + (j - 1) * 4;
    const int nA    = (j == 0) ? 3 : 4;

    // Load local side matrices (fast trig ok: depth <= 15)
    float Lm[4][12];
#pragma unroll
    for (int i = 0; i < 4; i++) {
        if (i < nA) {
            const float4 d = __ldg((const float4*)(dofs + 4 * (sbase + first + i)));
            bond_ht<true>(d.x, d.y, d.z, d.w, Lm[i]);
        }
    }

    // kin ids (coalesced-ish: consecutive atoms across lanes of a warp)
    int kid[4];
#pragma unroll
    for (int i = 0; i < 4; i++)
        if (i < nA) kid[i] = __ldg(&kin_id[1 + sbase + first + i]);

    // Segment product S. Lane 0 walks + emits while building (its inclusive
    // value IS its final cumulative product).
    float S[12];
    if (j == 0) {
        compose(s_pref, &s_scan[l * 12], S);       // S = G (gen0 global)
        const int pk = __ldg(&kin_id[c + 1]);
        out[3*pk + 0] = S[3]; out[3*pk + 1] = S[7]; out[3*pk + 2] = S[11];
#pragma unroll
        for (int i = 0; i < 3; i++) {
            float C[12]; compose(S, Lm[i], C); mat_copy(S, C);
            out[3*kid[i] + 0] = S[3];
            out[3*kid[i] + 1] = S[7];
            out[3*kid[i] + 2] = S[11];
        }
    } else {
        mat_copy(S, Lm[0]);
#pragma unroll
        for (int i = 1; i < 4; i++) {
            float C[12]; compose(S, Lm[i], C); mat_copy(S, C);
        }
    }

    // Width-4 inclusive scan over S (2 steps), uniform across warp
#pragma unroll
    for (int off = 1; off < 4; off <<= 1) {
        float Q[12], C[12];
        shfl_up_mat(Q, S, off, 4);
        compose(Q, S, C);
        if (j >= off) mat_copy(S, C);
    }

    // Start for lane j>0 = inclusive value of lane j-1
    float X[12];
    shfl_up_mat(X, S, 1, 4);

    if (j > 0) {
        float cur[12];
        mat_copy(cur, X);
#pragma unroll
        for (int i = 0; i < 4; i++) {
            float C[12]; compose(cur, Lm[i], C); mat_copy(cur, C);
            out[3*kid[i] + 0] = cur[3];
            out[3*kid[i] + 1] = cur[7];
            out[3*kid[i] + 2] = cur[11];
        }
    }
}

extern "C" void kernel_launch(void* const* d_in, const int* in_sizes, int n_in,
                              void* d_out, int out_size) {
    const float* dofs   = (const float*)d_in[0];   // (NATM-1)*4
    const int*   kin_id = (const int*)  d_in[8];   // NATM
    float*       out    = (float*)d_out;           // (NATM-1)*3

    k_totals<<<NBLK, CHUNK>>>(dofs);
    k_apply<<<NBLK, K2_THR>>>(dofs, kin_id, out);
}